// round 4
// baseline (speedup 1.0000x reference)
#include <cuda_runtime.h>
#include <math.h>

#define B_    2
#define L_    256
#define D_    256
#define DI_   512
#define N_    32
#define R_    16
#define KK_   4
#define M_    16
#define NB_   7
#define DOUT_ 76416
#define BL    (B_*L_)

// ---------------- scratch (static device memory; no allocs) ----------------
__device__ float g_res[BL*D_];
__device__ float g_h  [BL*D_];
__device__ float g_xz [BL*2*DI_];
__device__ float g_xc [BL*DI_];
__device__ float g_dbl[BL*(R_+N_)];
__device__ float g_dt [BL*DI_];
__device__ float g_y  [BL*DI_];
__device__ float g_gy [BL*DI_];
__device__ float g_Zre[B_*M_*DI_];
__device__ float g_Zim[B_*M_*DI_];
__device__ float g_cs [M_*L_];
__device__ float g_sn [M_*L_];

// ---------------- packed f32x2 helpers ----------------
typedef unsigned long long u64t;
union F4U { float4 f; u64t u[2]; };
__device__ __forceinline__ void unpack2(u64t v, float& lo, float& hi) {
    asm("mov.b64 {%0,%1},%2;" : "=f"(lo), "=f"(hi) : "l"(v));
}
__device__ __forceinline__ void ffma2(u64t& d, u64t a, u64t b) {
    asm("fma.rn.f32x2 %0,%1,%2,%0;" : "+l"(d) : "l"(a), "l"(b));
}

// ---------------- twiddle table ----------------
__global__ void twiddle_kernel() {
    int i = blockIdx.x * blockDim.x + threadIdx.x;
    if (i < M_*L_) {
        int f = i / L_, t = i % L_;
        int ft = (f * t) % L_;                       // keep argument small for accuracy
        float ang = 6.283185307179586f * (float)ft / (float)L_;
        float s, c;
        sincosf(ang, &s, &c);
        g_cs[i] = c; g_sn[i] = s;
    }
}

// ---------------- residual add + layernorm ----------------
__global__ void ln_kernel(const float* __restrict__ addsrc,
                          const float* __restrict__ w,
                          const float* __restrict__ b, int first) {
    int row = blockIdx.x;
    int tid = threadIdx.x;                            // 256 == D_
    float r = addsrc[row*D_ + tid];
    if (!first) r += g_res[row*D_ + tid];
    g_res[row*D_ + tid] = r;

    __shared__ float red[256];
    red[tid] = r; __syncthreads();
    #pragma unroll
    for (int s = 128; s > 0; s >>= 1) { if (tid < s) red[tid] += red[tid + s]; __syncthreads(); }
    float mu = red[0] * (1.f / D_);
    __syncthreads();
    float dc = r - mu;
    red[tid] = dc * dc; __syncthreads();
    #pragma unroll
    for (int s = 128; s > 0; s >>= 1) { if (tid < s) red[tid] += red[tid + s]; __syncthreads(); }
    float inv = rsqrtf(red[0] * (1.f / D_) + 1e-5f);
    g_h[row*D_ + tid] = dc * inv * w[tid] + b[tid];
}

// ---------------- SGEMM: C[M,N] = A[M,K] * W[N,K]^T ----------------
// Block tile 64(M) x 128(N), BK=16, 256 threads, per-thread 8x4 via f32x2.
// A stored duplicated in smem (pairs) so FFMA2 broadcast operands need no MOVs.
// Double-buffered smem, one __syncthreads per K-tile.
// Requires: M % 64 == 0, K % 16 == 0, lda/ldb % 4 == 0. N arbitrary unless EXACT.
template<bool EXACT>
__global__ void sgemm_nt(const float* __restrict__ A, int lda,
                         const float* __restrict__ W, int ldb,
                         float* __restrict__ C, int ldc,
                         int Mtot, int N, int K) {
    __shared__ float As[2][16][128];   // duplicated pairs: As[k][2m]=As[k][2m+1]=a
    __shared__ float Bs[2][16][128];
    int tid = threadIdx.x;
    int tx = tid & 31, ty = tid >> 5;                 // tx: n/4 (32), ty: m/8 (8)
    int m0 = blockIdx.y * 64, n0 = blockIdx.x * 128;

    // load-assignment indices
    int lrow = tid >> 2;                              // 0..63
    int lkq  = (tid & 3) * 4;                         // 0,4,8,12
    const float* Aptr = A + (m0 + lrow)*lda + lkq;
    const float* Bp0  = W + (n0 + lrow)*ldb + lkq;
    const float* Bp1  = W + (n0 + 64 + lrow)*ldb + lkq;
    bool bok0 = EXACT || (n0 + lrow      < N);
    bool bok1 = EXACT || (n0 + 64 + lrow < N);

    float4 ra, rb0, rb1;
    const float4 fz = make_float4(0.f, 0.f, 0.f, 0.f);

    // prologue: load tile 0
    ra  = *(const float4*)Aptr;
    rb0 = bok0 ? *(const float4*)Bp0 : fz;
    rb1 = bok1 ? *(const float4*)Bp1 : fz;
    {
        #pragma unroll
        for (int e = 0; e < 4; e++) {
            float va = (&ra.x)[e];
            As[0][lkq+e][2*lrow]   = va;
            As[0][lkq+e][2*lrow+1] = va;
            Bs[0][lkq+e][lrow]      = (&rb0.x)[e];
            Bs[0][lkq+e][64 + lrow] = (&rb1.x)[e];
        }
    }
    __syncthreads();

    u64t acc[8][2] = {};
    int NT = K / 16;
    for (int it = 0; it < NT; it++) {
        int cur = it & 1;
        if (it + 1 < NT) {
            int k0 = (it + 1) * 16;
            ra  = *(const float4*)(Aptr + k0);
            rb0 = bok0 ? *(const float4*)(Bp0 + k0) : fz;
            rb1 = bok1 ? *(const float4*)(Bp1 + k0) : fz;
        }
        #pragma unroll
        for (int k = 0; k < 16; k++) {
            F4U a0, a1, a2, a3, bb;
            a0.f = *(const float4*)&As[cur][k][ty*16];
            a1.f = *(const float4*)&As[cur][k][ty*16 + 4];
            a2.f = *(const float4*)&As[cur][k][ty*16 + 8];
            a3.f = *(const float4*)&As[cur][k][ty*16 + 12];
            bb.f = *(const float4*)&Bs[cur][k][tx*4];
            u64t bp0 = bb.u[0], bp1 = bb.u[1];
            ffma2(acc[0][0], a0.u[0], bp0); ffma2(acc[0][1], a0.u[0], bp1);
            ffma2(acc[1][0], a0.u[1], bp0); ffma2(acc[1][1], a0.u[1], bp1);
            ffma2(acc[2][0], a1.u[0], bp0); ffma2(acc[2][1], a1.u[0], bp1);
            ffma2(acc[3][0], a1.u[1], bp0); ffma2(acc[3][1], a1.u[1], bp1);
            ffma2(acc[4][0], a2.u[0], bp0); ffma2(acc[4][1], a2.u[0], bp1);
            ffma2(acc[5][0], a2.u[1], bp0); ffma2(acc[5][1], a2.u[1], bp1);
            ffma2(acc[6][0], a3.u[0], bp0); ffma2(acc[6][1], a3.u[0], bp1);
            ffma2(acc[7][0], a3.u[1], bp0); ffma2(acc[7][1], a3.u[1], bp1);
        }
        if (it + 1 < NT) {
            int nxt = cur ^ 1;
            #pragma unroll
            for (int e = 0; e < 4; e++) {
                float va = (&ra.x)[e];
                As[nxt][lkq+e][2*lrow]   = va;
                As[nxt][lkq+e][2*lrow+1] = va;
                Bs[nxt][lkq+e][lrow]      = (&rb0.x)[e];
                Bs[nxt][lkq+e][64 + lrow] = (&rb1.x)[e];
            }
            __syncthreads();
        }
    }

    #pragma unroll
    for (int i = 0; i < 8; i++) {
        int m = m0 + ty*8 + i;
        #pragma unroll
        for (int jp = 0; jp < 2; jp++) {
            float lo, hi;
            unpack2(acc[i][jp], lo, hi);
            int n = n0 + tx*4 + jp*2;
            if (EXACT || n + 1 < N) {
                *(float2*)&C[m*ldc + n] = make_float2(lo, hi);
            } else if (n < N) {
                C[m*ldc + n] = lo;
            }
        }
    }
}

// ---------------- depthwise causal conv (K=4) + bias + SiLU ----------------
__global__ void conv_kernel(const float* __restrict__ cw, const float* __restrict__ cb) {
    int idx = blockIdx.x * blockDim.x + threadIdx.x;
    if (idx >= BL*DI_) return;
    int d = idx % DI_;
    int row = idx / DI_;
    int l = row % L_, b = row / L_;
    float acc = cb[d];
    #pragma unroll
    for (int k = 0; k < KK_; k++) {
        int t = l + k - (KK_ - 1);
        if (t >= 0) acc += g_xz[(b*L_ + t)*(2*DI_) + d] * cw[d*KK_ + k];
    }
    g_xc[idx] = acc * (1.f / (1.f + __expf(-acc)));
}

// ---------------- dt = softplus(dbl[:, :16] @ dt_w^T + dt_b) ----------------
__global__ void dt_kernel(const float* __restrict__ dtw, const float* __restrict__ dtb) {
    int idx = blockIdx.x * blockDim.x + threadIdx.x;
    if (idx >= BL*DI_) return;
    int d = idx % DI_, row = idx / DI_;
    float v = dtb[d];
    const float* dr = g_dbl + row*(R_+N_);
    #pragma unroll
    for (int r = 0; r < R_; r++) v += dr[r] * dtw[d*R_ + r];
    g_dt[idx] = fmaxf(v, 0.f) + log1pf(__expf(-fabsf(v)));
}

// ---------------- sequential SSM scan: one warp per (b,d), lane = n ----------------
__global__ void scan_kernel(const float* __restrict__ A_log,
                            const float* __restrict__ Cmat,
                            const float* __restrict__ Dvec) {
    int gw = (blockIdx.x * blockDim.x + threadIdx.x) >> 5;
    int lane = threadIdx.x & 31;
    if (gw >= B_*DI_) return;
    int b = gw / DI_, d = gw % DI_;
    float a  = -__expf(A_log[d*N_ + lane]);
    float c  = Cmat[d*N_ + lane];
    float Dv = Dvec[d];
    float h  = 0.f;
    const float* dtp = g_dt  + b*L_*DI_ + d;
    const float* xp  = g_xc  + b*L_*DI_ + d;
    const float* Bp  = g_dbl + b*L_*(R_+N_) + R_ + lane;
    float* yp = g_y + b*L_*DI_ + d;
    for (int t = 0; t < L_; t++) {
        float dtv = dtp[t*DI_];
        float xv  = xp[t*DI_];
        float bm  = Bp[t*(R_+N_)];
        h = __expf(dtv * a) * h + (dtv * xv) * bm;
        float p = h * c;
        #pragma unroll
        for (int o = 16; o > 0; o >>= 1) p += __shfl_xor_sync(0xffffffffu, p, o);
        if (lane == 0) yp[t*DI_] = p + Dv * xv;
    }
}

// ---------------- forward truncated DFT + spectral weight multiply ----------------
// grid = B_*M_ blocks, 512 threads; block handles one (b, f), thread = d
__global__ void dft_fwd_kernel(const float* __restrict__ spec_r,
                               const float* __restrict__ spec_i) {
    int b = blockIdx.x / M_, f = blockIdx.x % M_;
    int d = threadIdx.x;
    __shared__ float cs[L_], sn[L_];
    for (int i = threadIdx.x; i < L_; i += 512) { cs[i] = g_cs[f*L_ + i]; sn[i] = g_sn[f*L_ + i]; }
    __syncthreads();
    float re = 0.f, im = 0.f;
    const float* xp = g_xc + b*L_*DI_ + d;
    #pragma unroll 4
    for (int t = 0; t < L_; t++) {
        float xv = xp[t*DI_];
        re += xv * cs[t];
        im -= xv * sn[t];
    }
    float wr = spec_r[d*M_ + f], wi = spec_i[d*M_ + f];
    g_Zre[(b*M_ + f)*DI_ + d] = re*wr - im*wi;
    g_Zim[(b*M_ + f)*DI_ + d] = re*wi + im*wr;
}

// ---------------- inverse truncated DFT + accumulate + gate ----------------
__global__ void dft_inv_gate_kernel() {
    int row = blockIdx.x;                             // b*L + l
    int b = row / L_, l = row % L_;
    int d = threadIdx.x;                              // 512
    __shared__ float c[M_], s[M_];
    if (threadIdx.x < M_) { c[threadIdx.x] = g_cs[threadIdx.x*L_ + l]; s[threadIdx.x] = g_sn[threadIdx.x*L_ + l]; }
    __syncthreads();
    float acc = g_Zre[(b*M_ + 0)*DI_ + d];            // Im(DC) dropped by irfft
    #pragma unroll
    for (int f = 1; f < M_; f++)
        acc += 2.f * (g_Zre[(b*M_ + f)*DI_ + d] * c[f] - g_Zim[(b*M_ + f)*DI_ + d] * s[f]);
    float yv = g_y[row*DI_ + d] + acc * (1.f / (float)L_);
    float z  = g_xz[row*(2*DI_) + DI_ + d];
    g_gy[row*DI_ + d] = yv * (z * (1.f / (1.f + __expf(-z))));
}

// ---------------- host driver ----------------
extern "C" void kernel_launch(void* const* d_in, const int* in_sizes, int n_in,
                              void* d_out, int out_size) {
    const float* x       = (const float*)d_in[0];
    const float* ln_w    = (const float*)d_in[1];
    const float* ln_b    = (const float*)d_in[2];
    const float* in_w    = (const float*)d_in[3];
    const float* conv_w  = (const float*)d_in[4];
    const float* conv_b  = (const float*)d_in[5];
    const float* xproj_w = (const float*)d_in[6];
    const float* dt_w    = (const float*)d_in[7];
    const float* dt_b    = (const float*)d_in[8];
    const float* A_log   = (const float*)d_in[9];
    const float* Cmat    = (const float*)d_in[10];
    const float* Dvec    = (const float*)d_in[11];
    const float* spec_r  = (const float*)d_in[12];
    const float* spec_i  = (const float*)d_in[13];
    const float* out_w   = (const float*)d_in[14];
    const float* fln_w   = (const float*)d_in[15];
    const float* fln_b   = (const float*)d_in[16];
    const float* f_in_w  = (const float*)d_in[17];
    const float* f_conv_w= (const float*)d_in[18];
    const float* f_conv_b= (const float*)d_in[19];
    const float* f_xproj = (const float*)d_in[20];
    const float* f_dt_w  = (const float*)d_in[21];
    const float* f_dt_b  = (const float*)d_in[22];
    const float* f_A_log = (const float*)d_in[23];
    const float* f_Cmat  = (const float*)d_in[24];
    const float* f_Dvec  = (const float*)d_in[25];
    const float* f_spec_r= (const float*)d_in[26];
    const float* f_spec_i= (const float*)d_in[27];
    const float* f_out_w = (const float*)d_in[28];

    float *h, *xz, *xc, *dbl, *gy;
    cudaGetSymbolAddress((void**)&h,   g_h);
    cudaGetSymbolAddress((void**)&xz,  g_xz);
    cudaGetSymbolAddress((void**)&xc,  g_xc);
    cudaGetSymbolAddress((void**)&dbl, g_dbl);
    cudaGetSymbolAddress((void**)&gy,  g_gy);

    twiddle_kernel<<<16, 256>>>();

    for (int i = 0; i < 8; i++) {
        bool fin = (i == 7);
        const float* lw  = fin ? fln_w    : ln_w    + i*D_;
        const float* lb  = fin ? fln_b    : ln_b    + i*D_;
        const float* iw  = fin ? f_in_w   : in_w    + i*2*DI_*D_;
        const float* cw  = fin ? f_conv_w : conv_w  + i*DI_*KK_;
        const float* cb  = fin ? f_conv_b : conv_b  + i*DI_;
        const float* xpw = fin ? f_xproj  : xproj_w + i*(R_+N_)*DI_;
        const float* dw  = fin ? f_dt_w   : dt_w    + i*DI_*R_;
        const float* db  = fin ? f_dt_b   : dt_b    + i*DI_;
        const float* al  = fin ? f_A_log  : A_log   + i*DI_*N_;
        const float* cm  = fin ? f_Cmat   : Cmat    + i*DI_*N_;
        const float* dv  = fin ? f_Dvec   : Dvec    + i*DI_;
        const float* sr  = fin ? f_spec_r : spec_r  + i*DI_*M_;
        const float* si  = fin ? f_spec_i : spec_i  + i*DI_*M_;
        const float* ow  = fin ? f_out_w  : out_w   + i*D_*DI_;
        int nout = fin ? DOUT_ : D_;
        float* cout = fin ? (float*)d_out : h;

        // residual add + layernorm
        ln_kernel<<<BL, D_>>>(i == 0 ? x : h, lw, lb, i == 0 ? 1 : 0);
        // in_proj: xz = h @ in_w^T   (512 x 1024, K=256)  N=1024 exact
        sgemm_nt<true><<<dim3(2*DI_/128, BL/64), 256>>>(h, D_, iw, D_, xz, 2*DI_, BL, 2*DI_, D_);
        // depthwise conv + SiLU
        conv_kernel<<<(BL*DI_ + 255)/256, 256>>>(cw, cb);
        // xproj: dbl = xc @ xproj_w^T  (512 x 48, K=512)  N=48 inexact
        sgemm_nt<false><<<dim3(1, BL/64), 256>>>(xc, DI_, xpw, DI_, dbl, R_+N_, BL, R_+N_, DI_);
        // dt
        dt_kernel<<<(BL*DI_ + 255)/256, 256>>>(dw, db);
        // SSM scan (writes y = scan + D*x)
        scan_kernel<<<(B_*DI_*32)/256, 256>>>(al, cm, dv);
        // spectral branch
        dft_fwd_kernel<<<B_*M_, 512>>>(sr, si);
        dft_inv_gate_kernel<<<BL, DI_>>>();
        // out projection: N = 256 (exact, 2 blocks) or 76416 (exact, 597 blocks)
        sgemm_nt<true><<<dim3(nout/128 + (nout%128 ? 1 : 0), BL/64), 256>>>(gy, DI_, ow, DI_, cout, nout, BL, nout, DI_);
    }
}

// round 6
// speedup vs baseline: 1.2430x; 1.2430x over previous
#include <cuda_runtime.h>
#include <cuda_bf16.h>
#include <math.h>
#include <stdint.h>

#define B_    2
#define L_    256
#define D_    256
#define DI_   512
#define N_    32
#define R_    16
#define KK_   4
#define M_    16
#define NB_   7
#define DOUT_ 76416
#define BL    (B_*L_)

// ---------------- scratch (static device memory; no allocs) ----------------
__device__ float g_res[BL*D_];
__device__ float g_h  [BL*D_];
__device__ float g_xz [BL*2*DI_];
__device__ float g_xc [BL*DI_];
__device__ float g_dbl[BL*(R_+N_)];
__device__ float g_dt [BL*DI_];
__device__ float g_y  [BL*DI_];
__device__ float g_gy [BL*DI_];
__device__ float g_Zre[B_*M_*DI_];
__device__ float g_Zim[B_*M_*DI_];
__device__ float g_cs [M_*L_];
__device__ float g_sn [M_*L_];
// split-bf16 operands for the final projection
__device__ __align__(16) __nv_bfloat16 g_Whi[(size_t)DOUT_*DI_];
__device__ __align__(16) __nv_bfloat16 g_Wlo[(size_t)DOUT_*DI_];
__device__ __align__(16) __nv_bfloat16 g_Ahi[BL*DI_];
__device__ __align__(16) __nv_bfloat16 g_Alo[BL*DI_];

// ---------------- packed f32x2 helpers (SIMT GEMM) ----------------
typedef unsigned long long u64t;
union F4U { float4 f; u64t u[2]; };
__device__ __forceinline__ void unpack2(u64t v, float& lo, float& hi) {
    asm("mov.b64 {%0,%1},%2;" : "=f"(lo), "=f"(hi) : "l"(v));
}
__device__ __forceinline__ void ffma2(u64t& d, u64t a, u64t b) {
    asm("fma.rn.f32x2 %0,%1,%2,%0;" : "+l"(d) : "l"(a), "l"(b));
}

// ---------------- cp.async helpers (base ISA, sm_80+) ----------------
__device__ __forceinline__ uint32_t s2u(const void* p) {
    uint32_t a;
    asm("{ .reg .u64 t; cvta.to.shared.u64 t, %1; cvt.u32.u64 %0, t; }" : "=r"(a) : "l"(p));
    return a;
}
__device__ __forceinline__ void cpasync16(void* dst, const void* src) {
    asm volatile("cp.async.cg.shared.global [%0], [%1], 16;" :: "r"(s2u(dst)), "l"(src));
}
#define CP_COMMIT() asm volatile("cp.async.commit_group;" ::: "memory")
#define CP_WAIT(n)  asm volatile("cp.async.wait_group %0;" :: "n"(n) : "memory")

// ---------------- warp mma (base ISA) ----------------
__device__ __forceinline__ void mma16816(float* c, const uint32_t* a, const uint32_t* b) {
    asm volatile(
        "mma.sync.aligned.m16n8k16.row.col.f32.bf16.bf16.f32 "
        "{%0,%1,%2,%3}, {%4,%5,%6,%7}, {%8,%9}, {%0,%1,%2,%3};"
        : "+f"(c[0]), "+f"(c[1]), "+f"(c[2]), "+f"(c[3])
        : "r"(a[0]), "r"(a[1]), "r"(a[2]), "r"(a[3]), "r"(b[0]), "r"(b[1]));
}

// ---------------- twiddle table ----------------
__global__ void twiddle_kernel() {
    int i = blockIdx.x * blockDim.x + threadIdx.x;
    if (i < M_*L_) {
        int f = i / L_, t = i % L_;
        int ft = (f * t) % L_;
        float ang = 6.283185307179586f * (float)ft / (float)L_;
        float s, c;
        sincosf(ang, &s, &c);
        g_cs[i] = c; g_sn[i] = s;
    }
}

// ---------------- split-bf16 conversions ----------------
__global__ void cvt_w_kernel(const float* __restrict__ W) {
    size_t i = (size_t)blockIdx.x * 256 + threadIdx.x;     // float4 index
    if (i >= (size_t)DOUT_*DI_/4) return;
    float4 v = ((const float4*)W)[i];
    __nv_bfloat16 h0 = __float2bfloat16(v.x), h1 = __float2bfloat16(v.y);
    __nv_bfloat16 h2 = __float2bfloat16(v.z), h3 = __float2bfloat16(v.w);
    __nv_bfloat16 l0 = __float2bfloat16(v.x - __bfloat162float(h0));
    __nv_bfloat16 l1 = __float2bfloat16(v.y - __bfloat162float(h1));
    __nv_bfloat16 l2 = __float2bfloat16(v.z - __bfloat162float(h2));
    __nv_bfloat16 l3 = __float2bfloat16(v.w - __bfloat162float(h3));
    ((__nv_bfloat162*)g_Whi)[i*2]   = __halves2bfloat162(h0, h1);
    ((__nv_bfloat162*)g_Whi)[i*2+1] = __halves2bfloat162(h2, h3);
    ((__nv_bfloat162*)g_Wlo)[i*2]   = __halves2bfloat162(l0, l1);
    ((__nv_bfloat162*)g_Wlo)[i*2+1] = __halves2bfloat162(l2, l3);
}
__global__ void cvt_a_kernel() {
    size_t i = (size_t)blockIdx.x * 256 + threadIdx.x;
    if (i >= (size_t)BL*DI_/4) return;
    float4 v = ((const float4*)g_gy)[i];
    __nv_bfloat16 h0 = __float2bfloat16(v.x), h1 = __float2bfloat16(v.y);
    __nv_bfloat16 h2 = __float2bfloat16(v.z), h3 = __float2bfloat16(v.w);
    __nv_bfloat16 l0 = __float2bfloat16(v.x - __bfloat162float(h0));
    __nv_bfloat16 l1 = __float2bfloat16(v.y - __bfloat162float(h1));
    __nv_bfloat16 l2 = __float2bfloat16(v.z - __bfloat162float(h2));
    __nv_bfloat16 l3 = __float2bfloat16(v.w - __bfloat162float(h3));
    ((__nv_bfloat162*)g_Ahi)[i*2]   = __halves2bfloat162(h0, h1);
    ((__nv_bfloat162*)g_Ahi)[i*2+1] = __halves2bfloat162(h2, h3);
    ((__nv_bfloat162*)g_Alo)[i*2]   = __halves2bfloat162(l0, l1);
    ((__nv_bfloat162*)g_Alo)[i*2+1] = __halves2bfloat162(l2, l3);
}

// ---------------- final projection via mma.sync (HMMA) ----------------
// C[512, DOUT] = A[512,512] @ W[DOUT,512]^T, split-bf16, 3 product passes folded
// into a 24-chunk K loop. CTA tile 128x128, 8 warps (2m x 4n), warp tile 64x32.
// smem rows padded to 72 bf16 (conflict-free fragment loads). cp.async 2-stage.
#define SMSTR 72
#define ABUF  (128*SMSTR)               // 9216 bf16
#define BUFSZ (2*ABUF)                  // A + W per buffer
#define OUT_SMEM (2*BUFSZ*2)            // bytes: 2 buffers * 18432 bf16 * 2B = 73728

__global__ __launch_bounds__(256) void out_mma_kernel(float* __restrict__ C) {
    extern __shared__ __nv_bfloat16 sm[];
    int tid = threadIdx.x, wid = tid >> 5, lane = tid & 31;
    int m0 = blockIdx.y * 128, n0 = blockIdx.x * 128;
    int wm = wid & 1, wn = wid >> 1;
    int g = lane >> 2, tig = lane & 3;

    const __nv_bfloat16* Asrcs[3] = { g_Ahi, g_Alo, g_Ahi };
    const __nv_bfloat16* Wsrcs[3] = { g_Whi, g_Whi, g_Wlo };

    int lr = tid >> 1, ls = tid & 1;                       // load row, half-segment

    // prefetch chunk 0
    {
        const __nv_bfloat16* Ap = Asrcs[0] + (size_t)(m0 + lr)*DI_ + ls*32;
        const __nv_bfloat16* Wp = Wsrcs[0] + (size_t)(n0 + lr)*DI_ + ls*32;
        __nv_bfloat16* Ad = sm + lr*SMSTR + ls*32;
        __nv_bfloat16* Wd = sm + ABUF + lr*SMSTR + ls*32;
        #pragma unroll
        for (int i = 0; i < 4; i++) {
            cpasync16(Ad + i*8, Ap + i*8);
            cpasync16(Wd + i*8, Wp + i*8);
        }
        CP_COMMIT();
    }

    float acc[4][4][4] = {};
    const int NT = 24;                                     // 3 passes x 8 chunks
    for (int it = 0; it < NT; it++) {
        int buf = it & 1;
        if (it + 1 < NT) {
            int p = (it + 1) >> 3, kc = (it + 1) & 7;
            const __nv_bfloat16* Ap = Asrcs[p] + (size_t)(m0 + lr)*DI_ + kc*64 + ls*32;
            const __nv_bfloat16* Wp = Wsrcs[p] + (size_t)(n0 + lr)*DI_ + kc*64 + ls*32;
            __nv_bfloat16* Ad = sm + (buf^1)*BUFSZ + lr*SMSTR + ls*32;
            __nv_bfloat16* Wd = sm + (buf^1)*BUFSZ + ABUF + lr*SMSTR + ls*32;
            #pragma unroll
            for (int i = 0; i < 4; i++) {
                cpasync16(Ad + i*8, Ap + i*8);
                cpasync16(Wd + i*8, Wp + i*8);
            }
            CP_COMMIT();
            CP_WAIT(1);
        } else {
            CP_WAIT(0);
        }
        __syncthreads();

        const __nv_bfloat16* Ab = sm + buf*BUFSZ;
        const __nv_bfloat16* Wb = Ab + ABUF;
        #pragma unroll
        for (int ks = 0; ks < 4; ks++) {
            uint32_t af[4][4], bfr[4][2];
            #pragma unroll
            for (int mt = 0; mt < 4; mt++) {
                const __nv_bfloat16* base = Ab + (wm*64 + mt*16 + g)*SMSTR + ks*16 + tig*2;
                af[mt][0] = *(const uint32_t*)(base);
                af[mt][1] = *(const uint32_t*)(base + 8*SMSTR);
                af[mt][2] = *(const uint32_t*)(base + 8);
                af[mt][3] = *(const uint32_t*)(base + 8*SMSTR + 8);
            }
            #pragma unroll
            for (int nt = 0; nt < 4; nt++) {
                const __nv_bfloat16* base = Wb + (wn*32 + nt*8 + g)*SMSTR + ks*16 + tig*2;
                bfr[nt][0] = *(const uint32_t*)(base);
                bfr[nt][1] = *(const uint32_t*)(base + 8);
            }
            #pragma unroll
            for (int mt = 0; mt < 4; mt++)
                #pragma unroll
                for (int nt = 0; nt < 4; nt++)
                    mma16816(acc[mt][nt], af[mt], bfr[nt]);
        }
        __syncthreads();
    }

    // epilogue: direct stores (c0,c1 contiguous -> float2)
    #pragma unroll
    for (int mt = 0; mt < 4; mt++) {
        int m = m0 + wm*64 + mt*16 + g;
        #pragma unroll
        for (int nt = 0; nt < 4; nt++) {
            int n = n0 + wn*32 + nt*8 + tig*2;
            *(float2*)(C + (size_t)m*DOUT_ + n)       = make_float2(acc[mt][nt][0], acc[mt][nt][1]);
            *(float2*)(C + (size_t)(m + 8)*DOUT_ + n) = make_float2(acc[mt][nt][2], acc[mt][nt][3]);
        }
    }
}

// ---------------- residual add + layernorm ----------------
__global__ void ln_kernel(const float* __restrict__ addsrc,
                          const float* __restrict__ w,
                          const float* __restrict__ b, int first) {
    int row = blockIdx.x;
    int tid = threadIdx.x;
    float r = addsrc[row*D_ + tid];
    if (!first) r += g_res[row*D_ + tid];
    g_res[row*D_ + tid] = r;

    __shared__ float red[256];
    red[tid] = r; __syncthreads();
    #pragma unroll
    for (int s = 128; s > 0; s >>= 1) { if (tid < s) red[tid] += red[tid + s]; __syncthreads(); }
    float mu = red[0] * (1.f / D_);
    __syncthreads();
    float dc = r - mu;
    red[tid] = dc * dc; __syncthreads();
    #pragma unroll
    for (int s = 128; s > 0; s >>= 1) { if (tid < s) red[tid] += red[tid + s]; __syncthreads(); }
    float inv = rsqrtf(red[0] * (1.f / D_) + 1e-5f);
    g_h[row*D_ + tid] = dc * inv * w[tid] + b[tid];
}

// ---------------- SIMT SGEMM for the small projections ----------------
template<bool EXACT>
__global__ void sgemm_nt(const float* __restrict__ A, int lda,
                         const float* __restrict__ W, int ldb,
                         float* __restrict__ C, int ldc,
                         int Mtot, int N, int K) {
    __shared__ float As[2][16][128];
    __shared__ float Bs[2][16][128];
    int tid = threadIdx.x;
    int tx = tid & 31, ty = tid >> 5;
    int m0 = blockIdx.y * 64, n0 = blockIdx.x * 128;

    int lrow = tid >> 2;
    int lkq  = (tid & 3) * 4;
    const float* Aptr = A + (m0 + lrow)*lda + lkq;
    const float* Bp0  = W + (n0 + lrow)*ldb + lkq;
    const float* Bp1  = W + (n0 + 64 + lrow)*ldb + lkq;
    bool bok0 = EXACT || (n0 + lrow      < N);
    bool bok1 = EXACT || (n0 + 64 + lrow < N);

    float4 ra, rb0, rb1;
    const float4 fz = make_float4(0.f, 0.f, 0.f, 0.f);

    ra  = *(const float4*)Aptr;
    rb0 = bok0 ? *(const float4*)Bp0 : fz;
    rb1 = bok1 ? *(const float4*)Bp1 : fz;
    #pragma unroll
    for (int e = 0; e < 4; e++) {
        float va = (&ra.x)[e];
        As[0][lkq+e][2*lrow]   = va;
        As[0][lkq+e][2*lrow+1] = va;
        Bs[0][lkq+e][lrow]      = (&rb0.x)[e];
        Bs[0][lkq+e][64 + lrow] = (&rb1.x)[e];
    }
    __syncthreads();

    u64t acc[8][2] = {};
    int NT = K / 16;
    for (int it = 0; it < NT; it++) {
        int cur = it & 1;
        if (it + 1 < NT) {
            int k0 = (it + 1) * 16;
            ra  = *(const float4*)(Aptr + k0);
            rb0 = bok0 ? *(const float4*)(Bp0 + k0) : fz;
            rb1 = bok1 ? *(const float4*)(Bp1 + k0) : fz;
        }
        #pragma unroll
        for (int k = 0; k < 16; k++) {
            F4U a0, a1, a2, a3, bb;
            a0.f = *(const float4*)&As[cur][k][ty*16];
            a1.f = *(const float4*)&As[cur][k][ty*16 + 4];
            a2.f = *(const float4*)&As[cur][k][ty*16 + 8];
            a3.f = *(const float4*)&As[cur][k][ty*16 + 12];
            bb.f = *(const float4*)&Bs[cur][k][tx*4];
            u64t bp0 = bb.u[0], bp1 = bb.u[1];
            ffma2(acc[0][0], a0.u[0], bp0); ffma2(acc[0][1], a0.u[0], bp1);
            ffma2(acc[1][0], a0.u[1], bp0); ffma2(acc[1][1], a0.u[1], bp1);
            ffma2(acc[2][0], a1.u[0], bp0); ffma2(acc[2][1], a1.u[0], bp1);
            ffma2(acc[3][0], a1.u[1], bp0); ffma2(acc[3][1], a1.u[1], bp1);
            ffma2(acc[4][0], a2.u[0], bp0); ffma2(acc[4][1], a2.u[0], bp1);
            ffma2(acc[5][0], a2.u[1], bp0); ffma2(acc[5][1], a2.u[1], bp1);
            ffma2(acc[6][0], a3.u[0], bp0); ffma2(acc[6][1], a3.u[0], bp1);
            ffma2(acc[7][0], a3.u[1], bp0); ffma2(acc[7][1], a3.u[1], bp1);
        }
        if (it + 1 < NT) {
            int nxt = cur ^ 1;
            #pragma unroll
            for (int e = 0; e < 4; e++) {
                float va = (&ra.x)[e];
                As[nxt][lkq+e][2*lrow]   = va;
                As[nxt][lkq+e][2*lrow+1] = va;
                Bs[nxt][lkq+e][lrow]      = (&rb0.x)[e];
                Bs[nxt][lkq+e][64 + lrow] = (&rb1.x)[e];
            }
            __syncthreads();
        }
    }

    #pragma unroll
    for (int i = 0; i < 8; i++) {
        int m = m0 + ty*8 + i;
        #pragma unroll
        for (int jp = 0; jp < 2; jp++) {
            float lo, hi;
            unpack2(acc[i][jp], lo, hi);
            int n = n0 + tx*4 + jp*2;
            if (EXACT || n + 1 < N) {
                *(float2*)&C[m*ldc + n] = make_float2(lo, hi);
            } else if (n < N) {
                C[m*ldc + n] = lo;
            }
        }
    }
}

// ---------------- depthwise causal conv (K=4) + bias + SiLU ----------------
__global__ void conv_kernel(const float* __restrict__ cw, const float* __restrict__ cb) {
    int idx = blockIdx.x * blockDim.x + threadIdx.x;
    if (idx >= BL*DI_) return;
    int d = idx % DI_;
    int row = idx / DI_;
    int l = row % L_, b = row / L_;
    float acc = cb[d];
    #pragma unroll
    for (int k = 0; k < KK_; k++) {
        int t = l + k - (KK_ - 1);
        if (t >= 0) acc += g_xz[(b*L_ + t)*(2*DI_) + d] * cw[d*KK_ + k];
    }
    g_xc[idx] = acc * (1.f / (1.f + __expf(-acc)));
}

// ---------------- dt = softplus(dbl[:, :16] @ dt_w^T + dt_b) ----------------
__global__ void dt_kernel(const float* __restrict__ dtw, const float* __restrict__ dtb) {
    int idx = blockIdx.x * blockDim.x + threadIdx.x;
    if (idx >= BL*DI_) return;
    int d = idx % DI_, row = idx / DI_;
    float v = dtb[d];
    const float* dr = g_dbl + row*(R_+N_);
    #pragma unroll
    for (int r = 0; r < R_; r++) v += dr[r] * dtw[d*R_ + r];
    g_dt[idx] = fmaxf(v, 0.f) + log1pf(__expf(-fabsf(v)));
}

// ---------------- sequential SSM scan: one warp per (b,d), lane = n ----------------
__global__ void scan_kernel(const float* __restrict__ A_log,
                            const float* __restrict__ Cmat,
                            const float* __restrict__ Dvec) {
    int gw = (blockIdx.x * blockDim.x + threadIdx.x) >> 5;
    int lane = threadIdx.x & 31;
    if (gw >= B_*DI_) return;
    int b = gw / DI_, d = gw % DI_;
    float a  = -__expf(A_log[d*N_ + lane]);
    float c  = Cmat[d*N_ + lane];
    float Dv = Dvec[d];
    float h  = 0.f;
    const float* dtp = g_dt  + b*L_*DI_ + d;
    const float* xp  = g_xc  + b*L_*DI_ + d;
    const float* Bp  = g_dbl + b*L_*(R_+N_) + R_ + lane;
    float* yp = g_y + b*L_*DI_ + d;
    for (int t = 0; t < L_; t++) {
        float dtv = dtp[t*DI_];
        float xv  = xp[t*DI_];
        float bm  = Bp[t*(R_+N_)];
        h = __expf(dtv * a) * h + (dtv * xv) * bm;
        float p = h * c;
        #pragma unroll
        for (int o = 16; o > 0; o >>= 1) p += __shfl_xor_sync(0xffffffffu, p, o);
        if (lane == 0) yp[t*DI_] = p + Dv * xv;
    }
}

// ---------------- forward truncated DFT + spectral weight multiply ----------------
__global__ void dft_fwd_kernel(const float* __restrict__ spec_r,
                               const float* __restrict__ spec_i) {
    int b = blockIdx.x / M_, f = blockIdx.x % M_;
    int d = threadIdx.x;
    __shared__ float cs[L_], sn[L_];
    for (int i = threadIdx.x; i < L_; i += 512) { cs[i] = g_cs[f*L_ + i]; sn[i] = g_sn[f*L_ + i]; }
    __syncthreads();
    float re = 0.f, im = 0.f;
    const float* xp = g_xc + b*L_*DI_ + d;
    #pragma unroll 4
    for (int t = 0; t < L_; t++) {
        float xv = xp[t*DI_];
        re += xv * cs[t];
        im -= xv * sn[t];
    }
    float wr = spec_r[d*M_ + f], wi = spec_i[d*M_ + f];
    g_Zre[(b*M_ + f)*DI_ + d] = re*wr - im*wi;
    g_Zim[(b*M_ + f)*DI_ + d] = re*wi + im*wr;
}

// ---------------- inverse truncated DFT + accumulate + gate ----------------
__global__ void dft_inv_gate_kernel() {
    int row = blockIdx.x;
    int b = row / L_, l = row % L_;
    int d = threadIdx.x;
    __shared__ float c[M_], s[M_];
    if (threadIdx.x < M_) { c[threadIdx.x] = g_cs[threadIdx.x*L_ + l]; s[threadIdx.x] = g_sn[threadIdx.x*L_ + l]; }
    __syncthreads();
    float acc = g_Zre[(b*M_ + 0)*DI_ + d];
    #pragma unroll
    for (int f = 1; f < M_; f++)
        acc += 2.f * (g_Zre[(b*M_ + f)*DI_ + d] * c[f] - g_Zim[(b*M_ + f)*DI_ + d] * s[f]);
    float yv = g_y[row*DI_ + d] + acc * (1.f / (float)L_);
    float z  = g_xz[row*(2*DI_) + DI_ + d];
    g_gy[row*DI_ + d] = yv * (z * (1.f / (1.f + __expf(-z))));
}

// ---------------- host driver ----------------
extern "C" void kernel_launch(void* const* d_in, const int* in_sizes, int n_in,
                              void* d_out, int out_size) {
    const float* x       = (const float*)d_in[0];
    const float* ln_w    = (const float*)d_in[1];
    const float* ln_b    = (const float*)d_in[2];
    const float* in_w    = (const float*)d_in[3];
    const float* conv_w  = (const float*)d_in[4];
    const float* conv_b  = (const float*)d_in[5];
    const float* xproj_w = (const float*)d_in[6];
    const float* dt_w    = (const float*)d_in[7];
    const float* dt_b    = (const float*)d_in[8];
    const float* A_log   = (const float*)d_in[9];
    const float* Cmat    = (const float*)d_in[10];
    const float* Dvec    = (const float*)d_in[11];
    const float* spec_r  = (const float*)d_in[12];
    const float* spec_i  = (const float*)d_in[13];
    const float* out_w   = (const float*)d_in[14];
    const float* fln_w   = (const float*)d_in[15];
    const float* fln_b   = (const float*)d_in[16];
    const float* f_in_w  = (const float*)d_in[17];
    const float* f_conv_w= (const float*)d_in[18];
    const float* f_conv_b= (const float*)d_in[19];
    const float* f_xproj = (const float*)d_in[20];
    const float* f_dt_w  = (const float*)d_in[21];
    const float* f_dt_b  = (const float*)d_in[22];
    const float* f_A_log = (const float*)d_in[23];
    const float* f_Cmat  = (const float*)d_in[24];
    const float* f_Dvec  = (const float*)d_in[25];
    const float* f_spec_r= (const float*)d_in[26];
    const float* f_spec_i= (const float*)d_in[27];
    const float* f_out_w = (const float*)d_in[28];

    float *h, *xz, *xc, *dbl, *gy;
    cudaGetSymbolAddress((void**)&h,   g_h);
    cudaGetSymbolAddress((void**)&xz,  g_xz);
    cudaGetSymbolAddress((void**)&xc,  g_xc);
    cudaGetSymbolAddress((void**)&dbl, g_dbl);
    cudaGetSymbolAddress((void**)&gy,  g_gy);

    cudaFuncSetAttribute(out_mma_kernel, cudaFuncAttributeMaxDynamicSharedMemorySize, OUT_SMEM);

    twiddle_kernel<<<16, 256>>>();
    cvt_w_kernel<<<(DOUT_*DI_/4 + 255)/256, 256>>>(f_out_w);   // once per launch

    for (int i = 0; i < 8; i++) {
        bool fin = (i == 7);
        const float* lw  = fin ? fln_w    : ln_w    + i*D_;
        const float* lb  = fin ? fln_b    : ln_b    + i*D_;
        const float* iw  = fin ? f_in_w   : in_w    + i*2*DI_*D_;
        const float* cw  = fin ? f_conv_w : conv_w  + i*DI_*KK_;
        const float* cb  = fin ? f_conv_b : conv_b  + i*DI_;
        const float* xpw = fin ? f_xproj  : xproj_w + i*(R_+N_)*DI_;
        const float* dw  = fin ? f_dt_w   : dt_w    + i*DI_*R_;
        const float* db  = fin ? f_dt_b   : dt_b    + i*DI_;
        const float* al  = fin ? f_A_log  : A_log   + i*DI_*N_;
        const float* cm  = fin ? f_Cmat   : Cmat    + i*DI_*N_;
        const float* dv  = fin ? f_Dvec   : Dvec    + i*DI_;
        const float* sr  = fin ? f_spec_r : spec_r  + i*DI_*M_;
        const float* si  = fin ? f_spec_i : spec_i  + i*DI_*M_;
        const float* ow  = fin ? f_out_w  : out_w   + i*D_*DI_;

        ln_kernel<<<BL, D_>>>(i == 0 ? x : h, lw, lb, i == 0 ? 1 : 0);
        sgemm_nt<true><<<dim3(2*DI_/128, BL/64), 256>>>(h, D_, iw, D_, xz, 2*DI_, BL, 2*DI_, D_);
        conv_kernel<<<(BL*DI_ + 255)/256, 256>>>(cw, cb);
        sgemm_nt<false><<<dim3(1, BL/64), 256>>>(xc, DI_, xpw, DI_, dbl, R_+N_, BL, R_+N_, DI_);
        dt_kernel<<<(BL*DI_ + 255)/256, 256>>>(dw, db);
        scan_kernel<<<(B_*DI_*32)/256, 256>>>(al, cm, dv);
        dft_fwd_kernel<<<B_*M_, 512>>>(sr, si);
        dft_inv_gate_kernel<<<BL, DI_>>>();

        if (!fin) {
            sgemm_nt<true><<<dim3(D_/128, BL/64), 256>>>(gy, DI_, ow, DI_, h, D_, BL, D_, DI_);
        } else {
            cvt_a_kernel<<<(BL*DI_/4 + 255)/256, 256>>>();
            out_mma_kernel<<<dim3(DOUT_/128, BL/128), 256, OUT_SMEM>>>((float*)d_out);
        }
    }
}

// round 10
// speedup vs baseline: 1.3455x; 1.0824x over previous
#include <cuda_runtime.h>
#include <cuda_bf16.h>
#include <math.h>
#include <stdint.h>

#define B_    2
#define L_    256
#define D_    256
#define DI_   512
#define N_    32
#define R_    16
#define KK_   4
#define M_    16
#define NB_   7
#define DOUT_ 76416
#define BL    (B_*L_)

// ---------------- scratch (static device memory; no allocs) ----------------
__device__ float g_res[BL*D_];
__device__ float g_h  [BL*D_];           // per-block out_proj result (fp32)
__device__ float g_xz [BL*2*DI_];
__device__ float g_xc [BL*DI_];
__device__ float g_dbl[BL*(R_+N_)];
__device__ float g_dt [BL*DI_];
__device__ float g_y  [BL*DI_];
__device__ float g_Zre[B_*M_*DI_];
__device__ float g_Zim[B_*M_*DI_];
__device__ float g_cs [M_*L_];
__device__ float g_sn [M_*L_];
// split-bf16 weights
__device__ __align__(16) __nv_bfloat16 g_Whi [(size_t)DOUT_*DI_];
__device__ __align__(16) __nv_bfloat16 g_Wlo [(size_t)DOUT_*DI_];
__device__ __align__(16) __nv_bfloat16 g_Wihi[NB_*2*DI_*D_];
__device__ __align__(16) __nv_bfloat16 g_Wilo[NB_*2*DI_*D_];
__device__ __align__(16) __nv_bfloat16 g_Wohi[NB_*D_*DI_];
__device__ __align__(16) __nv_bfloat16 g_Wolo[NB_*D_*DI_];
// split-bf16 activations (shared by h[512x256] and gy[512x512] phases)
__device__ __align__(16) __nv_bfloat16 g_Ahi[BL*DI_];
__device__ __align__(16) __nv_bfloat16 g_Alo[BL*DI_];

// ---------------- cp.async helpers (base ISA) ----------------
__device__ __forceinline__ uint32_t s2u(const void* p) {
    uint32_t a;
    asm("{ .reg .u64 t; cvta.to.shared.u64 t, %1; cvt.u32.u64 %0, t; }" : "=r"(a) : "l"(p));
    return a;
}
__device__ __forceinline__ void cpasync16(void* dst, const void* src) {
    asm volatile("cp.async.cg.shared.global [%0], [%1], 16;" :: "r"(s2u(dst)), "l"(src));
}
#define CP_COMMIT() asm volatile("cp.async.commit_group;" ::: "memory")
#define CP_WAIT(n)  asm volatile("cp.async.wait_group %0;" :: "n"(n) : "memory")

// ---------------- warp mma (base ISA) ----------------
__device__ __forceinline__ void mma16816(float* c, const uint32_t* a, const uint32_t* b) {
    asm volatile(
        "mma.sync.aligned.m16n8k16.row.col.f32.bf16.bf16.f32 "
        "{%0,%1,%2,%3}, {%4,%5,%6,%7}, {%8,%9}, {%0,%1,%2,%3};"
        : "+f"(c[0]), "+f"(c[1]), "+f"(c[2]), "+f"(c[3])
        : "r"(a[0]), "r"(a[1]), "r"(a[2]), "r"(a[3]), "r"(b[0]), "r"(b[1]));
}

// ---------------- twiddle table ----------------
__global__ void twiddle_kernel() {
    int i = blockIdx.x * blockDim.x + threadIdx.x;
    if (i < M_*L_) {
        int f = i / L_, t = i % L_;
        int ft = (f * t) % L_;
        float ang = 6.283185307179586f * (float)ft / (float)L_;
        float s, c;
        sincosf(ang, &s, &c);
        g_cs[i] = c; g_sn[i] = s;
    }
}

// ---------------- generic split conversion ----------------
__global__ void cvt_split(const float* __restrict__ src,
                          __nv_bfloat16* __restrict__ hi,
                          __nv_bfloat16* __restrict__ lo, size_t n4) {
    size_t i = (size_t)blockIdx.x * 256 + threadIdx.x;
    if (i >= n4) return;
    float4 v = ((const float4*)src)[i];
    __nv_bfloat16 h0 = __float2bfloat16(v.x), h1 = __float2bfloat16(v.y);
    __nv_bfloat16 h2 = __float2bfloat16(v.z), h3 = __float2bfloat16(v.w);
    __nv_bfloat16 l0 = __float2bfloat16(v.x - __bfloat162float(h0));
    __nv_bfloat16 l1 = __float2bfloat16(v.y - __bfloat162float(h1));
    __nv_bfloat16 l2 = __float2bfloat16(v.z - __bfloat162float(h2));
    __nv_bfloat16 l3 = __float2bfloat16(v.w - __bfloat162float(h3));
    ((__nv_bfloat162*)hi)[i*2]   = __halves2bfloat162(h0, h1);
    ((__nv_bfloat162*)hi)[i*2+1] = __halves2bfloat162(h2, h3);
    ((__nv_bfloat162*)lo)[i*2]   = __halves2bfloat162(l0, l1);
    ((__nv_bfloat162*)lo)[i*2+1] = __halves2bfloat162(l2, l3);
}

// ---------------- split-bf16 HMMA GEMM ----------------
// C[512, N] = A[512,K] @ W[N,K]^T via 3 passes (AhiWhi + AloWhi + AhiWlo).
// CTA tile 128x128, 8 warps (2m x 4n), warp tile 64x32, K chunk 64, 2-stage.
// Grid: x = M-tile (varies fastest -> W tile reuse in L2), y = N-tile.
#define SMSTR 72
#define ABUF  (128*SMSTR)
#define BUFSZ (2*ABUF)
#define GEMM_SMEM (2*BUFSZ*2)

__global__ __launch_bounds__(256) void bgemm_kernel(
    const __nv_bfloat16* __restrict__ Ahi, const __nv_bfloat16* __restrict__ Alo,
    const __nv_bfloat16* __restrict__ Whi, const __nv_bfloat16* __restrict__ Wlo,
    float* __restrict__ C, int K, int ldc) {
    extern __shared__ __nv_bfloat16 sm[];
    int tid = threadIdx.x, wid = tid >> 5, lane = tid & 31;
    int m0 = blockIdx.x * 128, n0 = blockIdx.y * 128;
    int wm = wid & 1, wn = wid >> 1;
    int g = lane >> 2, tig = lane & 3;
    int lr = tid >> 1, ls = tid & 1;
    int KC = K >> 6, NT = 3 * KC;

    // prefetch chunk 0 (pass 0: Ahi x Whi)
    {
        const __nv_bfloat16* Ap = Ahi + (size_t)(m0 + lr)*K + ls*32;
        const __nv_bfloat16* Wp = Whi + (size_t)(n0 + lr)*K + ls*32;
        __nv_bfloat16* Ad = sm + lr*SMSTR + ls*32;
        __nv_bfloat16* Wd = sm + ABUF + lr*SMSTR + ls*32;
        #pragma unroll
        for (int i = 0; i < 4; i++) {
            cpasync16(Ad + i*8, Ap + i*8);
            cpasync16(Wd + i*8, Wp + i*8);
        }
        CP_COMMIT();
    }

    float acc[4][4][4] = {};
    for (int it = 0; it < NT; it++) {
        int buf = it & 1;
        if (it + 1 < NT) {
            int nit = it + 1;
            int p = nit / KC, kc = nit - p*KC;
            const __nv_bfloat16* Ab = (p == 1) ? Alo : Ahi;
            const __nv_bfloat16* Wb = (p == 2) ? Wlo : Whi;
            const __nv_bfloat16* Ap = Ab + (size_t)(m0 + lr)*K + kc*64 + ls*32;
            const __nv_bfloat16* Wp = Wb + (size_t)(n0 + lr)*K + kc*64 + ls*32;
            __nv_bfloat16* Ad = sm + (buf^1)*BUFSZ + lr*SMSTR + ls*32;
            __nv_bfloat16* Wd = sm + (buf^1)*BUFSZ + ABUF + lr*SMSTR + ls*32;
            #pragma unroll
            for (int i = 0; i < 4; i++) {
                cpasync16(Ad + i*8, Ap + i*8);
                cpasync16(Wd + i*8, Wp + i*8);
            }
            CP_COMMIT();
            CP_WAIT(1);
        } else {
            CP_WAIT(0);
        }
        __syncthreads();

        const __nv_bfloat16* Ab = sm + buf*BUFSZ;
        const __nv_bfloat16* Wb = Ab + ABUF;
        #pragma unroll
        for (int ks = 0; ks < 4; ks++) {
            uint32_t af[4][4], bfr[4][2];
            #pragma unroll
            for (int mt = 0; mt < 4; mt++) {
                const __nv_bfloat16* base = Ab + (wm*64 + mt*16 + g)*SMSTR + ks*16 + tig*2;
                af[mt][0] = *(const uint32_t*)(base);
                af[mt][1] = *(const uint32_t*)(base + 8*SMSTR);
                af[mt][2] = *(const uint32_t*)(base + 8);
                af[mt][3] = *(const uint32_t*)(base + 8*SMSTR + 8);
            }
            #pragma unroll
            for (int nt = 0; nt < 4; nt++) {
                const __nv_bfloat16* base = Wb + (wn*32 + nt*8 + g)*SMSTR + ks*16 + tig*2;
                bfr[nt][0] = *(const uint32_t*)(base);
                bfr[nt][1] = *(const uint32_t*)(base + 8);
            }
            #pragma unroll
            for (int mt = 0; mt < 4; mt++)
                #pragma unroll
                for (int nt = 0; nt < 4; nt++)
                    mma16816(acc[mt][nt], af[mt], bfr[nt]);
        }
        __syncthreads();
    }

    #pragma unroll
    for (int mt = 0; mt < 4; mt++) {
        int m = m0 + wm*64 + mt*16 + g;
        #pragma unroll
        for (int nt = 0; nt < 4; nt++) {
            int n = n0 + wn*32 + nt*8 + tig*2;
            *(float2*)(C + (size_t)m*ldc + n)       = make_float2(acc[mt][nt][0], acc[mt][nt][1]);
            *(float2*)(C + (size_t)(m + 8)*ldc + n) = make_float2(acc[mt][nt][2], acc[mt][nt][3]);
        }
    }
}

// ---------------- residual add + layernorm -> split bf16 h ----------------
__global__ void ln_kernel(const float* __restrict__ addsrc,
                          const float* __restrict__ w,
                          const float* __restrict__ b, int first) {
    int row = blockIdx.x;
    int tid = threadIdx.x;                            // 256 == D_
    float r = addsrc[row*D_ + tid];
    if (!first) r += g_res[row*D_ + tid];
    g_res[row*D_ + tid] = r;

    __shared__ float red[256];
    red[tid] = r; __syncthreads();
    #pragma unroll
    for (int s = 128; s > 0; s >>= 1) { if (tid < s) red[tid] += red[tid + s]; __syncthreads(); }
    float mu = red[0] * (1.f / D_);
    __syncthreads();
    float dc = r - mu;
    red[tid] = dc * dc; __syncthreads();
    #pragma unroll
    for (int s = 128; s > 0; s >>= 1) { if (tid < s) red[tid] += red[tid + s]; __syncthreads(); }
    float inv = rsqrtf(red[0] * (1.f / D_) + 1e-5f);
    float hv = dc * inv * w[tid] + b[tid];
    __nv_bfloat16 hh = __float2bfloat16(hv);
    g_Ahi[row*D_ + tid] = hh;
    g_Alo[row*D_ + tid] = __float2bfloat16(hv - __bfloat162float(hh));
}

// ---------------- fused depthwise conv + SiLU + xproj + dt: one CTA per row ----------------
__global__ void conv_xproj_dt_kernel(const float* __restrict__ cw,
                                     const float* __restrict__ cb,
                                     const float* __restrict__ xpw,
                                     const float* __restrict__ dtw,
                                     const float* __restrict__ dtb) {
    int row = blockIdx.x;                             // b*L + l
    int tid = threadIdx.x;                            // 256
    int l = row % L_, b = row / L_;
    __shared__ float xr[DI_];
    __shared__ float db[R_+N_];

    // depthwise causal conv (correlation) + bias + SiLU; 2 channels per thread
    #pragma unroll
    for (int q = 0; q < 2; q++) {
        int d = tid + q*256;
        float acc = cb[d];
        #pragma unroll
        for (int k = 0; k < KK_; k++) {
            int t = l + k - (KK_ - 1);
            if (t >= 0) acc += g_xz[(b*L_ + t)*(2*DI_) + d] * cw[d*KK_ + k];
        }
        float v = acc * (1.f / (1.f + __expf(-acc)));
        xr[d] = v;
        g_xc[row*DI_ + d] = v;
    }
    __syncthreads();

    // xproj: 48 warp-dots of K=512
    int wid = tid >> 5, lane = tid & 31;
    for (int c = wid; c < R_+N_; c += 8) {
        const float* wc = xpw + c*DI_;
        float s = 0.f;
        #pragma unroll
        for (int j = 0; j < 16; j++) s += xr[lane + 32*j] * wc[lane + 32*j];
        #pragma unroll
        for (int o = 16; o > 0; o >>= 1) s += __shfl_xor_sync(0xffffffffu, s, o);
        if (lane == 0) { db[c] = s; g_dbl[row*(R_+N_) + c] = s; }
    }
    __syncthreads();

    // dt = softplus(dbl[:R] @ dt_w^T + dt_b)
    #pragma unroll
    for (int q = 0; q < 2; q++) {
        int d = tid + q*256;
        float v = dtb[d];
        #pragma unroll
        for (int r = 0; r < R_; r++) v += db[r] * dtw[d*R_ + r];
        g_dt[row*DI_ + d] = fmaxf(v, 0.f) + log1pf(__expf(-fabsf(v)));
    }
}

// ---------------- sequential SSM scan: one warp per (b,d), lane = n ----------------
__global__ void scan_kernel(const float* __restrict__ A_log,
                            const float* __restrict__ Cmat,
                            const float* __restrict__ Dvec) {
    int gw = (blockIdx.x * blockDim.x + threadIdx.x) >> 5;
    int lane = threadIdx.x & 31;
    if (gw >= B_*DI_) return;
    int b = gw / DI_, d = gw % DI_;
    float a  = -__expf(A_log[d*N_ + lane]);
    float c  = Cmat[d*N_ + lane];
    float Dv = Dvec[d];
    float h  = 0.f;
    const float* dtp = g_dt  + b*L_*DI_ + d;
    const float* xp  = g_xc  + b*L_*DI_ + d;
    const float* Bp  = g_dbl + b*L_*(R_+N_) + R_ + lane;
    float* yp = g_y + b*L_*DI_ + d;
    for (int t = 0; t < L_; t++) {
        float dtv = dtp[t*DI_];
        float xv  = xp[t*DI_];
        float bm  = Bp[t*(R_+N_)];
        h = __expf(dtv * a) * h + (dtv * xv) * bm;
        float p = h * c;
        #pragma unroll
        for (int o = 16; o > 0; o >>= 1) p += __shfl_xor_sync(0xffffffffu, p, o);
        if (lane == 0) yp[t*DI_] = p + Dv * xv;
    }
}

// ---------------- forward truncated DFT + spectral weight multiply ----------------
__global__ void dft_fwd_kernel(const float* __restrict__ spec_r,
                               const float* __restrict__ spec_i) {
    int b = blockIdx.x / M_, f = blockIdx.x % M_;
    int d = threadIdx.x;                              // 512
    __shared__ float cs[L_], sn[L_];
    for (int i = threadIdx.x; i < L_; i += 512) { cs[i] = g_cs[f*L_ + i]; sn[i] = g_sn[f*L_ + i]; }
    __syncthreads();
    float re = 0.f, im = 0.f;
    const float* xp = g_xc + b*L_*DI_ + d;
    #pragma unroll 4
    for (int t = 0; t < L_; t++) {
        float xv = xp[t*DI_];
        re += xv * cs[t];
        im -= xv * sn[t];
    }
    float wr = spec_r[d*M_ + f], wi = spec_i[d*M_ + f];
    g_Zre[(b*M_ + f)*DI_ + d] = re*wr - im*wi;
    g_Zim[(b*M_ + f)*DI_ + d] = re*wi + im*wr;
}

// ---------------- inverse truncated DFT + accumulate + gate -> split bf16 gy ----------------
__global__ void dft_inv_gate_kernel() {
    int row = blockIdx.x;
    int b = row / L_, l = row % L_;
    int d = threadIdx.x;                              // 512
    __shared__ float c[M_], s[M_];
    if (threadIdx.x < M_) { c[threadIdx.x] = g_cs[threadIdx.x*L_ + l]; s[threadIdx.x] = g_sn[threadIdx.x*L_ + l]; }
    __syncthreads();
    float acc = g_Zre[(b*M_ + 0)*DI_ + d];            // Im(DC) dropped by irfft
    #pragma unroll
    for (int f = 1; f < M_; f++)
        acc += 2.f * (g_Zre[(b*M_ + f)*DI_ + d] * c[f] - g_Zim[(b*M_ + f)*DI_ + d] * s[f]);
    float yv = g_y[row*DI_ + d] + acc * (1.f / (float)L_);
    float z  = g_xz[row*(2*DI_) + DI_ + d];
    float gv = yv * (z * (1.f / (1.f + __expf(-z))));
    __nv_bfloat16 gh = __float2bfloat16(gv);
    g_Ahi[row*DI_ + d] = gh;
    g_Alo[row*DI_ + d] = __float2bfloat16(gv - __bfloat162float(gh));
}

// ---------------- host driver ----------------
extern "C" void kernel_launch(void* const* d_in, const int* in_sizes, int n_in,
                              void* d_out, int out_size) {
    const float* x       = (const float*)d_in[0];
    const float* ln_w    = (const float*)d_in[1];
    const float* ln_b    = (const float*)d_in[2];
    const float* in_w    = (const float*)d_in[3];
    const float* conv_w  = (const float*)d_in[4];
    const float* conv_b  = (const float*)d_in[5];
    const float* xproj_w = (const float*)d_in[6];
    const float* dt_w    = (const float*)d_in[7];
    const float* dt_b    = (const float*)d_in[8];
    const float* A_log   = (const float*)d_in[9];
    const float* Cmat    = (const float*)d_in[10];
    const float* Dvec    = (const float*)d_in[11];
    const float* spec_r  = (const float*)d_in[12];
    const float* spec_i  = (const float*)d_in[13];
    const float* out_w   = (const float*)d_in[14];
    const float* fln_w   = (const float*)d_in[15];
    const float* fln_b   = (const float*)d_in[16];
    const float* f_in_w  = (const float*)d_in[17];
    const float* f_conv_w= (const float*)d_in[18];
    const float* f_conv_b= (const float*)d_in[19];
    const float* f_xproj = (const float*)d_in[20];
    const float* f_dt_w  = (const float*)d_in[21];
    const float* f_dt_b  = (const float*)d_in[22];
    const float* f_A_log = (const float*)d_in[23];
    const float* f_Cmat  = (const float*)d_in[24];
    const float* f_Dvec  = (const float*)d_in[25];
    const float* f_spec_r= (const float*)d_in[26];
    const float* f_spec_i= (const float*)d_in[27];
    const float* f_out_w = (const float*)d_in[28];

    float *h, *xz;
    cudaGetSymbolAddress((void**)&h,  g_h);
    cudaGetSymbolAddress((void**)&xz, g_xz);
    __nv_bfloat16 *Whi, *Wlo, *Wihi, *Wilo, *Wohi, *Wolo, *Ahi, *Alo;
    cudaGetSymbolAddress((void**)&Whi,  g_Whi);
    cudaGetSymbolAddress((void**)&Wlo,  g_Wlo);
    cudaGetSymbolAddress((void**)&Wihi, g_Wihi);
    cudaGetSymbolAddress((void**)&Wilo, g_Wilo);
    cudaGetSymbolAddress((void**)&Wohi, g_Wohi);
    cudaGetSymbolAddress((void**)&Wolo, g_Wolo);
    cudaGetSymbolAddress((void**)&Ahi,  g_Ahi);
    cudaGetSymbolAddress((void**)&Alo,  g_Alo);

    cudaFuncSetAttribute(bgemm_kernel, cudaFuncAttributeMaxDynamicSharedMemorySize, GEMM_SMEM);

    twiddle_kernel<<<16, 256>>>();
    {   // one-time weight splits
        size_t n4 = (size_t)DOUT_*DI_/4;
        cvt_split<<<(unsigned)((n4 + 255)/256), 256>>>(f_out_w, Whi, Wlo, n4);
        size_t n4i = (size_t)NB_*2*DI_*D_/4;
        cvt_split<<<(unsigned)((n4i + 255)/256), 256>>>(in_w, Wihi, Wilo, n4i);
        size_t n4o = (size_t)NB_*D_*DI_/4;
        cvt_split<<<(unsigned)((n4o + 255)/256), 256>>>(out_w, Wohi, Wolo, n4o);
    }

    for (int i = 0; i < 8; i++) {
        bool fin = (i == 7);
        const float* lw  = fin ? fln_w    : ln_w    + i*D_;
        const float* lb  = fin ? fln_b    : ln_b    + i*D_;
        const float* cw  = fin ? f_conv_w : conv_w  + i*DI_*KK_;
        const float* cb  = fin ? f_conv_b : conv_b  + i*DI_;
        const float* xpw = fin ? f_xproj  : xproj_w + i*(R_+N_)*DI_;
        const float* dw  = fin ? f_dt_w   : dt_w    + i*DI_*R_;
        const float* db  = fin ? f_dt_b   : dt_b    + i*DI_;
        const float* al  = fin ? f_A_log  : A_log   + i*DI_*N_;
        const float* cm  = fin ? f_Cmat   : Cmat    + i*DI_*N_;
        const float* dv  = fin ? f_Dvec   : Dvec    + i*DI_;
        const float* sr  = fin ? f_spec_r : spec_r  + i*DI_*M_;
        const float* si  = fin ? f_spec_i : spec_i  + i*DI_*M_;

        // residual add + layernorm (writes split h)
        ln_kernel<<<BL, D_>>>(i == 0 ? x : h, lw, lb, i == 0 ? 1 : 0);

        const __nv_bfloat16 *iwh, *iwl;
        if (fin) {
            // block 0's region already consumed; reuse it for f_in_w
            size_t n4f = (size_t)2*DI_*D_/4;
            cvt_split<<<(unsigned)((n4f + 255)/256), 256>>>(f_in_w, Wihi, Wilo, n4f);
            iwh = Wihi; iwl = Wilo;
        } else {
            iwh = Wihi + (size_t)i*2*DI_*D_;
            iwl = Wilo + (size_t)i*2*DI_*D_;
        }
        // in_proj: xz = h @ in_w^T   (512x1024, K=256); grid x = M-tiles
        bgemm_kernel<<<dim3(4, 2*DI_/128), 256, GEMM_SMEM>>>(Ahi, Alo, iwh, iwl, xz, D_, 2*DI_);
        conv_xproj_dt_kernel<<<BL, 256>>>(cw, cb, xpw, dw, db);
        scan_kernel<<<(B_*DI_*32)/256, 256>>>(al, cm, dv);
        dft_fwd_kernel<<<B_*M_, 512>>>(sr, si);
        dft_inv_gate_kernel<<<BL, DI_>>>();   // writes split gy

        if (!fin) {
            const __nv_bfloat16* owh = Wohi + (size_t)i*D_*DI_;
            const __nv_bfloat16* owl = Wolo + (size_t)i*D_*DI_;
            bgemm_kernel<<<dim3(4, D_/128), 256, GEMM_SMEM>>>(Ahi, Alo, owh, owl, h, DI_, D_);
        } else {
            bgemm_kernel<<<dim3(4, DOUT_/128), 256, GEMM_SMEM>>>(Ahi, Alo, Whi, Wlo, (float*)d_out, DI_, DOUT_);
        }
    }
}

// round 13
// speedup vs baseline: 1.4343x; 1.0660x over previous
#include <cuda_runtime.h>
#include <cuda_bf16.h>
#include <math.h>
#include <stdint.h>

#define B_    2
#define L_    256
#define D_    256
#define DI_   512
#define N_    32
#define R_    16
#define KK_   4
#define M_    16
#define NB_   7
#define DOUT_ 76416
#define BL    (B_*L_)

// ---------------- scratch (static device memory; no allocs) ----------------
__device__ float g_res[BL*D_];
__device__ float g_h  [BL*D_];           // per-block out_proj result (fp32)
__device__ float g_xz [BL*2*DI_];
__device__ float g_xc [BL*DI_];
__device__ float g_dbl[BL*(R_+N_)];
__device__ float g_dt [BL*DI_];
__device__ float g_y  [BL*DI_];
__device__ float g_Zre[B_*M_*DI_];
__device__ float g_Zim[B_*M_*DI_];
__device__ float g_cs [M_*L_];
__device__ float g_sn [M_*L_];
// split-bf16 activations (shared by h[512x256] and gy[512x512] phases)
__device__ __align__(16) __nv_bfloat16 g_Ahi[BL*DI_];
__device__ __align__(16) __nv_bfloat16 g_Alo[BL*DI_];

// ---------------- cp.async helpers (base ISA) ----------------
__device__ __forceinline__ uint32_t s2u(const void* p) {
    uint32_t a;
    asm("{ .reg .u64 t; cvta.to.shared.u64 t, %1; cvt.u32.u64 %0, t; }" : "=r"(a) : "l"(p));
    return a;
}
__device__ __forceinline__ void cpasync16(void* dst, const void* src) {
    asm volatile("cp.async.cg.shared.global [%0], [%1], 16;" :: "r"(s2u(dst)), "l"(src));
}
#define CP_COMMIT() asm volatile("cp.async.commit_group;" ::: "memory")
#define CP_WAIT(n)  asm volatile("cp.async.wait_group %0;" :: "n"(n) : "memory")

// ---------------- warp mma (base ISA) ----------------
__device__ __forceinline__ void mma16816(float* c, const uint32_t* a, const uint32_t* b) {
    asm volatile(
        "mma.sync.aligned.m16n8k16.row.col.f32.bf16.bf16.f32 "
        "{%0,%1,%2,%3}, {%4,%5,%6,%7}, {%8,%9}, {%0,%1,%2,%3};"
        : "+f"(c[0]), "+f"(c[1]), "+f"(c[2]), "+f"(c[3])
        : "r"(a[0]), "r"(a[1]), "r"(a[2]), "r"(a[3]), "r"(b[0]), "r"(b[1]));
}
__device__ __forceinline__ uint32_t pack_bf2(__nv_bfloat16 a, __nv_bfloat16 b) {
    __nv_bfloat162 t = __halves2bfloat162(a, b);
    return *(uint32_t*)&t;
}

// ---------------- twiddle table ----------------
__global__ void twiddle_kernel() {
    int i = blockIdx.x * blockDim.x + threadIdx.x;
    if (i < M_*L_) {
        int f = i / L_, t = i % L_;
        int ft = (f * t) % L_;
        float ang = 6.283185307179586f * (float)ft / (float)L_;
        float s, c;
        sincosf(ang, &s, &c);
        g_cs[i] = c; g_sn[i] = s;
    }
}

// ---------------- split-bf16 HMMA GEMM, fp32 weights converted in-kernel ----------------
// C[512, N] = A[512,K] @ W[N,K]^T. Chunk-major: per 64-K chunk, W loaded fp32,
// hi/lo fragments built in registers, 3 products (AhiWhi+AloWhi+AhiWlo) accumulated.
// CTA tile 128x128, 8 warps (2m x 4n), warp tile 64x32, 2-stage cp.async.
// Grid: x = M-tile (varies fastest -> W tile reuse in L2), y = N-tile.
#define SMSTR 72                           // bf16 stride for A tiles
#define WSTR  68                           // fp32 stride for W staging
#define WST_BYTES (128*WSTR*4)             // 34816
#define AT_BYTES  (128*SMSTR*2)            // 18432
#define BUF_BYTES (WST_BYTES + 2*AT_BYTES) // 71680
#define GEMM_SMEM (2*BUF_BYTES)            // 143360

__global__ __launch_bounds__(256) void bgemm_f32w(
    const __nv_bfloat16* __restrict__ Ahi, const __nv_bfloat16* __restrict__ Alo,
    const float* __restrict__ Wf,
    float* __restrict__ C, int K, int ldc) {
    extern __shared__ char smc[];
    int tid = threadIdx.x, wid = tid >> 5, lane = tid & 31;
    int m0 = blockIdx.x * 128, n0 = blockIdx.y * 128;
    int wm = wid & 1, wn = wid >> 1;
    int g = lane >> 2, tig = lane & 3;
    int lr = tid >> 1, ls = tid & 1;
    int KC = K >> 6;

    // per-chunk loader: W fp32 (32KB) + Ahi/Alo bf16 (16KB each)
    auto load_chunk = [&](int kc, int buf) {
        char* base = smc + buf*BUF_BYTES;
        const float* Wp = Wf + (size_t)(n0 + lr)*K + kc*64 + ls*32;
        float* Wd = (float*)base + lr*WSTR + ls*32;
        #pragma unroll
        for (int i = 0; i < 8; i++) cpasync16(Wd + i*4, Wp + i*4);
        const __nv_bfloat16* Aph = Ahi + (size_t)(m0 + lr)*K + kc*64 + ls*32;
        const __nv_bfloat16* Apl = Alo + (size_t)(m0 + lr)*K + kc*64 + ls*32;
        __nv_bfloat16* Adh = (__nv_bfloat16*)(base + WST_BYTES) + lr*SMSTR + ls*32;
        __nv_bfloat16* Adl = (__nv_bfloat16*)(base + WST_BYTES + AT_BYTES) + lr*SMSTR + ls*32;
        #pragma unroll
        for (int i = 0; i < 4; i++) {
            cpasync16(Adh + i*8, Aph + i*8);
            cpasync16(Adl + i*8, Apl + i*8);
        }
        CP_COMMIT();
    };

    load_chunk(0, 0);

    float acc[4][4][4] = {};
    for (int kc = 0; kc < KC; kc++) {
        int buf = kc & 1;
        if (kc + 1 < KC) { load_chunk(kc + 1, buf ^ 1); CP_WAIT(1); }
        else             { CP_WAIT(0); }
        __syncthreads();

        char* base = smc + buf*BUF_BYTES;
        const float* Ws = (const float*)base;
        const __nv_bfloat16* Ash = (const __nv_bfloat16*)(base + WST_BYTES);
        const __nv_bfloat16* Asl = (const __nv_bfloat16*)(base + WST_BYTES + AT_BYTES);

        #pragma unroll
        for (int ks = 0; ks < 4; ks++) {
            // A fragments (hi & lo)
            uint32_t ah[4][4], al[4][4];
            #pragma unroll
            for (int mt = 0; mt < 4; mt++) {
                const __nv_bfloat16* bh = Ash + (wm*64 + mt*16 + g)*SMSTR + ks*16 + tig*2;
                ah[mt][0] = *(const uint32_t*)(bh);
                ah[mt][1] = *(const uint32_t*)(bh + 8*SMSTR);
                ah[mt][2] = *(const uint32_t*)(bh + 8);
                ah[mt][3] = *(const uint32_t*)(bh + 8*SMSTR + 8);
                const __nv_bfloat16* bl = Asl + (wm*64 + mt*16 + g)*SMSTR + ks*16 + tig*2;
                al[mt][0] = *(const uint32_t*)(bl);
                al[mt][1] = *(const uint32_t*)(bl + 8*SMSTR);
                al[mt][2] = *(const uint32_t*)(bl + 8);
                al[mt][3] = *(const uint32_t*)(bl + 8*SMSTR + 8);
            }
            // W fragments: fp32 -> (hi, lo) in registers
            uint32_t bh[4][2], blo[4][2];
            #pragma unroll
            for (int nt = 0; nt < 4; nt++) {
                const float* wb = Ws + (wn*32 + nt*8 + g)*WSTR + ks*16 + tig*2;
                float2 w0 = *(const float2*)(wb);
                float2 w1 = *(const float2*)(wb + 8);
                __nv_bfloat16 h00 = __float2bfloat16(w0.x), h01 = __float2bfloat16(w0.y);
                __nv_bfloat16 h10 = __float2bfloat16(w1.x), h11 = __float2bfloat16(w1.y);
                bh[nt][0]  = pack_bf2(h00, h01);
                bh[nt][1]  = pack_bf2(h10, h11);
                blo[nt][0] = pack_bf2(__float2bfloat16(w0.x - __bfloat162float(h00)),
                                      __float2bfloat16(w0.y - __bfloat162float(h01)));
                blo[nt][1] = pack_bf2(__float2bfloat16(w1.x - __bfloat162float(h10)),
                                      __float2bfloat16(w1.y - __bfloat162float(h11)));
            }
            // 3 products
            #pragma unroll
            for (int mt = 0; mt < 4; mt++)
                #pragma unroll
                for (int nt = 0; nt < 4; nt++)
                    mma16816(acc[mt][nt], ah[mt], bh[nt]);
            #pragma unroll
            for (int mt = 0; mt < 4; mt++)
                #pragma unroll
                for (int nt = 0; nt < 4; nt++)
                    mma16816(acc[mt][nt], al[mt], bh[nt]);
            #pragma unroll
            for (int mt = 0; mt < 4; mt++)
                #pragma unroll
                for (int nt = 0; nt < 4; nt++)
                    mma16816(acc[mt][nt], ah[mt], blo[nt]);
        }
        __syncthreads();
    }

    #pragma unroll
    for (int mt = 0; mt < 4; mt++) {
        int m = m0 + wm*64 + mt*16 + g;
        #pragma unroll
        for (int nt = 0; nt < 4; nt++) {
            int n = n0 + wn*32 + nt*8 + tig*2;
            *(float2*)(C + (size_t)m*ldc + n)       = make_float2(acc[mt][nt][0], acc[mt][nt][1]);
            *(float2*)(C + (size_t)(m + 8)*ldc + n) = make_float2(acc[mt][nt][2], acc[mt][nt][3]);
        }
    }
}

// ---------------- residual add + layernorm -> split bf16 h ----------------
__global__ void ln_kernel(const float* __restrict__ addsrc,
                          const float* __restrict__ w,
                          const float* __restrict__ b, int first) {
    int row = blockIdx.x;
    int tid = threadIdx.x;                            // 256 == D_
    float r = addsrc[row*D_ + tid];
    if (!first) r += g_res[row*D_ + tid];
    g_res[row*D_ + tid] = r;

    __shared__ float red[256];
    red[tid] = r; __syncthreads();
    #pragma unroll
    for (int s = 128; s > 0; s >>= 1) { if (tid < s) red[tid] += red[tid + s]; __syncthreads(); }
    float mu = red[0] * (1.f / D_);
    __syncthreads();
    float dc = r - mu;
    red[tid] = dc * dc; __syncthreads();
    #pragma unroll
    for (int s = 128; s > 0; s >>= 1) { if (tid < s) red[tid] += red[tid + s]; __syncthreads(); }
    float inv = rsqrtf(red[0] * (1.f / D_) + 1e-5f);
    float hv = dc * inv * w[tid] + b[tid];
    __nv_bfloat16 hh = __float2bfloat16(hv);
    g_Ahi[row*D_ + tid] = hh;
    g_Alo[row*D_ + tid] = __float2bfloat16(hv - __bfloat162float(hh));
}

// ---------------- fused depthwise conv + SiLU + xproj + dt: one CTA per row ----------------
__global__ void conv_xproj_dt_kernel(const float* __restrict__ cw,
                                     const float* __restrict__ cb,
                                     const float* __restrict__ xpw,
                                     const float* __restrict__ dtw,
                                     const float* __restrict__ dtb) {
    int row = blockIdx.x;                             // b*L + l
    int tid = threadIdx.x;                            // 256
    int l = row % L_, b = row / L_;
    __shared__ float xr[DI_];
    __shared__ float db[R_+N_];

    // depthwise causal conv (correlation) + bias + SiLU; 2 channels per thread
    #pragma unroll
    for (int q = 0; q < 2; q++) {
        int d = tid + q*256;
        float acc = cb[d];
        #pragma unroll
        for (int k = 0; k < KK_; k++) {
            int t = l + k - (KK_ - 1);
            if (t >= 0) acc += g_xz[(b*L_ + t)*(2*DI_) + d] * cw[d*KK_ + k];
        }
        float v = acc * (1.f / (1.f + __expf(-acc)));
        xr[d] = v;
        g_xc[row*DI_ + d] = v;
    }
    __syncthreads();

    // xproj: 48 warp-dots of K=512
    int wid = tid >> 5, lane = tid & 31;
    for (int c = wid; c < R_+N_; c += 8) {
        const float* wc = xpw + c*DI_;
        float s = 0.f;
        #pragma unroll
        for (int j = 0; j < 16; j++) s += xr[lane + 32*j] * wc[lane + 32*j];
        #pragma unroll
        for (int o = 16; o > 0; o >>= 1) s += __shfl_xor_sync(0xffffffffu, s, o);
        if (lane == 0) { db[c] = s; g_dbl[row*(R_+N_) + c] = s; }
    }
    __syncthreads();

    // dt = softplus(dbl[:R] @ dt_w^T + dt_b)
    #pragma unroll
    for (int q = 0; q < 2; q++) {
        int d = tid + q*256;
        float v = dtb[d];
        #pragma unroll
        for (int r = 0; r < R_; r++) v += db[r] * dtw[d*R_ + r];
        g_dt[row*DI_ + d] = fmaxf(v, 0.f) + log1pf(__expf(-fabsf(v)));
    }
}

// ---------------- sequential SSM scan: one warp per (b,d), lane = n ----------------
__global__ void scan_kernel(const float* __restrict__ A_log,
                            const float* __restrict__ Cmat,
                            const float* __restrict__ Dvec) {
    int gw = (blockIdx.x * blockDim.x + threadIdx.x) >> 5;
    int lane = threadIdx.x & 31;
    if (gw >= B_*DI_) return;
    int b = gw / DI_, d = gw % DI_;
    float a  = -__expf(A_log[d*N_ + lane]);
    float c  = Cmat[d*N_ + lane];
    float Dv = Dvec[d];
    float h  = 0.f;
    const float* dtp = g_dt  + b*L_*DI_ + d;
    const float* xp  = g_xc  + b*L_*DI_ + d;
    const float* Bp  = g_dbl + b*L_*(R_+N_) + R_ + lane;
    float* yp = g_y + b*L_*DI_ + d;
    for (int t = 0; t < L_; t++) {
        float dtv = dtp[t*DI_];
        float xv  = xp[t*DI_];
        float bm  = Bp[t*(R_+N_)];
        h = __expf(dtv * a) * h + (dtv * xv) * bm;
        float p = h * c;
        #pragma unroll
        for (int o = 16; o > 0; o >>= 1) p += __shfl_xor_sync(0xffffffffu, p, o);
        if (lane == 0) yp[t*DI_] = p + Dv * xv;
    }
}

// ---------------- forward truncated DFT + spectral weight multiply ----------------
__global__ void dft_fwd_kernel(const float* __restrict__ spec_r,
                               const float* __restrict__ spec_i) {
    int b = blockIdx.x / M_, f = blockIdx.x % M_;
    int d = threadIdx.x;                              // 512
    __shared__ float cs[L_], sn[L_];
    for (int i = threadIdx.x; i < L_; i += 512) { cs[i] = g_cs[f*L_ + i]; sn[i] = g_sn[f*L_ + i]; }
    __syncthreads();
    float re = 0.f, im = 0.f;
    const float* xp = g_xc + b*L_*DI_ + d;
    #pragma unroll 4
    for (int t = 0; t < L_; t++) {
        float xv = xp[t*DI_];
        re += xv * cs[t];
        im -= xv * sn[t];
    }
    float wr = spec_r[d*M_ + f], wi = spec_i[d*M_ + f];
    g_Zre[(b*M_ + f)*DI_ + d] = re*wr - im*wi;
    g_Zim[(b*M_ + f)*DI_ + d] = re*wi + im*wr;
}

// ---------------- inverse truncated DFT + accumulate + gate -> split bf16 gy ----------------
__global__ void dft_inv_gate_kernel() {
    int row = blockIdx.x;
    int b = row / L_, l = row % L_;
    int d = threadIdx.x;                              // 512
    __shared__ float c[M_], s[M_];
    if (threadIdx.x < M_) { c[threadIdx.x] = g_cs[threadIdx.x*L_ + l]; s[threadIdx.x] = g_sn[threadIdx.x*L_ + l]; }
    __syncthreads();
    float acc = g_Zre[(b*M_ + 0)*DI_ + d];            // Im(DC) dropped by irfft
    #pragma unroll
    for (int f = 1; f < M_; f++)
        acc += 2.f * (g_Zre[(b*M_ + f)*DI_ + d] * c[f] - g_Zim[(b*M_ + f)*DI_ + d] * s[f]);
    float yv = g_y[row*DI_ + d] + acc * (1.f / (float)L_);
    float z  = g_xz[row*(2*DI_) + DI_ + d];
    float gv = yv * (z * (1.f / (1.f + __expf(-z))));
    __nv_bfloat16 gh = __float2bfloat16(gv);
    g_Ahi[row*DI_ + d] = gh;
    g_Alo[row*DI_ + d] = __float2bfloat16(gv - __bfloat162float(gh));
}

// ---------------- host driver ----------------
extern "C" void kernel_launch(void* const* d_in, const int* in_sizes, int n_in,
                              void* d_out, int out_size) {
    const float* x       = (const float*)d_in[0];
    const float* ln_w    = (const float*)d_in[1];
    const float* ln_b    = (const float*)d_in[2];
    const float* in_w    = (const float*)d_in[3];
    const float* conv_w  = (const float*)d_in[4];
    const float* conv_b  = (const float*)d_in[5];
    const float* xproj_w = (const float*)d_in[6];
    const float* dt_w    = (const float*)d_in[7];
    const float* dt_b    = (const float*)d_in[8];
    const float* A_log   = (const float*)d_in[9];
    const float* Cmat    = (const float*)d_in[10];
    const float* Dvec    = (const float*)d_in[11];
    const float* spec_r  = (const float*)d_in[12];
    const float* spec_i  = (const float*)d_in[13];
    const float* out_w   = (const float*)d_in[14];
    const float* fln_w   = (const float*)d_in[15];
    const float* fln_b   = (const float*)d_in[16];
    const float* f_in_w  = (const float*)d_in[17];
    const float* f_conv_w= (const float*)d_in[18];
    const float* f_conv_b= (const float*)d_in[19];
    const float* f_xproj = (const float*)d_in[20];
    const float* f_dt_w  = (const float*)d_in[21];
    const float* f_dt_b  = (const float*)d_in[22];
    const float* f_A_log = (const float*)d_in[23];
    const float* f_Cmat  = (const float*)d_in[24];
    const float* f_Dvec  = (const float*)d_in[25];
    const float* f_spec_r= (const float*)d_in[26];
    const float* f_spec_i= (const float*)d_in[27];
    const float* f_out_w = (const float*)d_in[28];

    float *h, *xz;
    cudaGetSymbolAddress((void**)&h,  g_h);
    cudaGetSymbolAddress((void**)&xz, g_xz);
    __nv_bfloat16 *Ahi, *Alo;
    cudaGetSymbolAddress((void**)&Ahi, g_Ahi);
    cudaGetSymbolAddress((void**)&Alo, g_Alo);

    cudaFuncSetAttribute(bgemm_f32w, cudaFuncAttributeMaxDynamicSharedMemorySize, GEMM_SMEM);

    twiddle_kernel<<<16, 256>>>();

    for (int i = 0; i < 8; i++) {
        bool fin = (i == 7);
        const float* lw  = fin ? fln_w    : ln_w    + i*D_;
        const float* lb  = fin ? fln_b    : ln_b    + i*D_;
        const float* iw  = fin ? f_in_w   : in_w    + i*2*DI_*D_;
        const float* cw  = fin ? f_conv_w : conv_w  + i*DI_*KK_;
        const float* cb  = fin ? f_conv_b : conv_b  + i*DI_;
        const float* xpw = fin ? f_xproj  : xproj_w + i*(R_+N_)*DI_;
        const float* dw  = fin ? f_dt_w   : dt_w    + i*DI_*R_;
        const float* db  = fin ? f_dt_b   : dt_b    + i*DI_;
        const float* al  = fin ? f_A_log  : A_log   + i*DI_*N_;
        const float* cm  = fin ? f_Cmat   : Cmat    + i*DI_*N_;
        const float* dv  = fin ? f_Dvec   : Dvec    + i*DI_;
        const float* sr  = fin ? f_spec_r : spec_r  + i*DI_*M_;
        const float* si  = fin ? f_spec_i : spec_i  + i*DI_*M_;
        const float* ow  = fin ? f_out_w  : out_w   + i*D_*DI_;

        // residual add + layernorm (writes split h)
        ln_kernel<<<BL, D_>>>(i == 0 ? x : h, lw, lb, i == 0 ? 1 : 0);
        // in_proj: xz = h @ in_w^T (512x1024, K=256); grid x = M-tiles
        bgemm_f32w<<<dim3(4, 2*DI_/128), 256, GEMM_SMEM>>>(Ahi, Alo, iw, xz, D_, 2*DI_);
        conv_xproj_dt_kernel<<<BL, 256>>>(cw, cb, xpw, dw, db);
        scan_kernel<<<(B_*DI_*32)/256, 256>>>(al, cm, dv);
        dft_fwd_kernel<<<B_*M_, 512>>>(sr, si);
        dft_inv_gate_kernel<<<BL, DI_>>>();   // writes split gy

        if (!fin) {
            bgemm_f32w<<<dim3(4, D_/128), 256, GEMM_SMEM>>>(Ahi, Alo, ow, h, DI_, D_);
        } else {
            bgemm_f32w<<<dim3(4, DOUT_/128), 256, GEMM_SMEM>>>(Ahi, Alo, ow, (float*)d_out, DI_, DOUT_);
        }
    }
}